// round 13
// baseline (speedup 1.0000x reference)
#include <cuda_runtime.h>

// QuixerCore — analytic collapse, single fused kernel (converged structure).
//
// Math (validated R8-R12, rel_err ~9e-7):
//  * CRX blocks are no-ops; only RY params [0..10] and [22..32] act.
//  * Token unitary = product of per-qubit RY with half-angle
//    h[t][q] = (A[t][q] + A[t][q+22]) / 2, A = emb @ W.T + b.
//  * _apply_lcu norm prefactor cancels -> acc = 21 weighted product states
//    (1 e0 + 4 single + 16 double); ff unitary folds in as +h_ff[q].
//  * poly_norm and final normalization cancel in exps = raw / ||acc||^2.
//  * Expectations factorize: per pair (a,b), per qubit:
//      d = ca·cb + sa·sb,  X = sa·cb + ca·sb,  Y = sa·cb − ca·sb,
//      Z = ca·cb − sa·sb;  contribution = W_pair · P · Prod_{q'≠q} d.
//
// Structure (384 threads = 12 warps):
//  warps 0..10 : Phase A — 2 W rows x 4 tokens per warp, 24 LDG.128 batched,
//                FFMA2 accumulation; packed f32x2 butterfly reduction.
//  warp 11     : scalar prep (lcu normalizer, 21 weights, angle bases).
//  barrier -> Phase B: 231 threads, __sincosf, tables stored as float2 (c,s).
//  barrier -> Phase C: 4 warps x 2 pairs/thread, single-pass d/X/Y/Z in regs,
//                3-level butterfly -> part[34][16].
//  barrier -> Phase D: 33 threads fold 16 partials each and divide.

namespace {

constexpr int NQ    = 11;
constexpr int NT    = 21;    // 1 + 4 + 16 product-state terms
constexpr int NPAIR = 231;   // NT*(NT+1)/2

__device__ __forceinline__ void ffma2(unsigned long long& acc,
                                      unsigned long long a,
                                      unsigned long long b) {
    asm("fma.rn.f32x2 %0, %1, %2, %0;" : "+l"(acc) : "l"(a), "l"(b));
}

__device__ __forceinline__ void fadd2(unsigned long long& acc,
                                      unsigned long long a) {
    asm("add.rn.f32x2 %0, %0, %1;" : "+l"(acc) : "l"(a));
}

__global__ void __launch_bounds__(384, 1) quixer_kernel(
    const float* __restrict__ emb,   // [32,512]
    const float* __restrict__ W,     // [44,512]
    const float* __restrict__ bias,  // [44]
    const float* __restrict__ qc,    // [3]
    const float* __restrict__ lre,   // [32]
    const float* __restrict__ lim,   // [32]
    const float* __restrict__ ffp,   // [44]
    float* __restrict__ out)         // [33]
{
    __shared__ float  rawA[4][22];       // raw dots (no bias); jj<11 -> param jj, else jj+11
    __shared__ float  hb0[NQ];           // ff half-angle base (term 0)
    __shared__ float  hb1[NQ];           // + 1x bias half-sum (terms 1..4)
    __shared__ float  hb2[NQ];           // + 2x bias half-sum (terms 5..20)
    __shared__ float2 cs2[NT][NQ];       // (cos, sin) per term per qubit
    __shared__ float  wre[NT], wim[NT];  // complex term weights
    __shared__ float  part[34][16];      // 4 warps x 4 lane-partials each

    const int tid  = threadIdx.x;
    const int lane = tid & 31;
    const int wid  = tid >> 5;

    if (wid < 11) {
        // ---- Phase A: 2 W rows x 4 tokens per warp; all 24 loads batched ----
        const int jj0 = 2 * wid;
        const int jj1 = 2 * wid + 1;
        const int j0  = (jj0 < NQ) ? jj0 : (jj0 + 11);
        const int j1  = (jj1 < NQ) ? jj1 : (jj1 + 11);
        const ulonglong2* W0 = reinterpret_cast<const ulonglong2*>(W + j0 * 512);
        const ulonglong2* W1 = reinterpret_cast<const ulonglong2*>(W + j1 * 512);

        ulonglong2 wv0[4], wv1[4], ev[4][4];
        #pragma unroll
        for (int k = 0; k < 4; k++) {
            wv0[k] = W0[lane + 32 * k];
            wv1[k] = W1[lane + 32 * k];
        }
        #pragma unroll
        for (int t = 0; t < 4; t++) {
            const ulonglong2* E = reinterpret_cast<const ulonglong2*>(emb + t * 512);
            #pragma unroll
            for (int k = 0; k < 4; k++) ev[t][k] = E[lane + 32 * k];
        }

        unsigned long long a0[4] = {0ull, 0ull, 0ull, 0ull};
        unsigned long long a1[4] = {0ull, 0ull, 0ull, 0ull};
        #pragma unroll
        for (int t = 0; t < 4; t++) {
            #pragma unroll
            for (int k = 0; k < 4; k++) {
                ffma2(a0[t], ev[t][k].x, wv0[k].x);
                ffma2(a0[t], ev[t][k].y, wv0[k].y);
                ffma2(a1[t], ev[t][k].x, wv1[k].x);
                ffma2(a1[t], ev[t][k].y, wv1[k].y);
            }
        }
        #pragma unroll
        for (int t = 0; t < 4; t++) {
            float2 f0 = *reinterpret_cast<float2*>(&a0[t]);
            float2 f1 = *reinterpret_cast<float2*>(&a1[t]);
            // pack (s0, s1) and butterfly with one f32x2 add per level
            float2 pr = make_float2(f0.x + f0.y, f1.x + f1.y);
            unsigned long long pk = *reinterpret_cast<unsigned long long*>(&pr);
            #pragma unroll
            for (int o = 16; o; o >>= 1) {
                unsigned int lo = __shfl_xor_sync(0xffffffffu, (unsigned int)pk, o);
                unsigned int hi = __shfl_xor_sync(0xffffffffu, (unsigned int)(pk >> 32), o);
                fadd2(pk, ((unsigned long long)hi << 32) | lo);
            }
            if (lane == 0) {
                float2 r = *reinterpret_cast<float2*>(&pk);
                rawA[t][jj0] = r.x;
                rawA[t][jj1] = r.y;
            }
        }
    } else {
        // ---- Warp 11: scalar prep, overlapped with Phase A ----
        float lr = lre[lane], li = lim[lane];
        float f1 = 0.f, f2 = 0.f, b1 = 0.f, b2 = 0.f;
        if (lane < NQ) {
            f1 = ffp[lane];  f2 = ffp[lane + 22];
            b1 = bias[lane]; b2 = bias[lane + 22];
        }
        const float q0 = qc[0], q1 = qc[1], q2 = qc[2];

        float v = hypotf(lr, li);
        #pragma unroll
        for (int o = 16; o; o >>= 1) v += __shfl_xor_sync(0xffffffffu, v, o);
        const float invS = 1.f / fmaxf(v, 1e-8f);   // all lanes hold the sum

        if (lane < NQ) {
            float hf = 0.5f * (f1 + f2);            // ff half-angle
            float bh = 0.5f * (b1 + b2);            // bias half-sum
            hb0[lane] = hf;
            hb1[lane] = hf + bh;
            hb2[lane] = hf + 2.f * bh;
        }
        if (lane < NT) {
            const int m = lane;
            float re, im;
            if (m == 0) {
                re = q0; im = 0.f;
            } else if (m < 5) {
                int s4 = m - 1;
                re = q1 * lre[s4] * invS;
                im = q1 * lim[s4] * invS;
            } else {
                int idx = m - 5;
                int t = idx >> 2, s4 = idx & 3;
                float ar = lre[t] * invS, ai = lim[t] * invS;
                float br = lre[s4] * invS, bi = lim[s4] * invS;
                re = q2 * (ar * br - ai * bi);
                im = q2 * (ar * bi + ai * br);
            }
            wre[m] = re;
            wim[m] = im;
        }
    }
    __syncthreads();

    // ---- Phase B: per-term (cos,sin) tables (231 threads), float2 packed ----
    if (tid < NT * NQ) {
        const int term = tid / NQ;
        const int q    = tid - term * NQ;
        float h;
        if (term == 0) {
            h = hb0[q];
        } else if (term < 5) {
            const int t = term - 1;
            h = hb1[q] + 0.5f * (rawA[t][q] + rawA[t][q + 11]);
        } else {
            const int idx = term - 5;
            const int t = idx >> 2, s4 = idx & 3;
            h = hb2[q] + 0.5f * (rawA[t][q] + rawA[t][q + 11])
                       + 0.5f * (rawA[s4][q] + rawA[s4][q + 11]);
        }
        float cv, sv;
        __sincosf(h, &sv, &cv);
        cs2[term][q] = make_float2(cv, sv);
    }
    __syncthreads();

    // ---- Phase C: 4 warps, 2 pairs per thread, single-pass elements ----
    if (wid < 4) {
        float acc[34];
        #pragma unroll
        for (int m = 0; m < 34; m++) acc[m] = 0.f;

        #pragma unroll
        for (int half = 0; half < 2; half++) {
            const int p = tid + 128 * half;
            if (p < NPAIR) {
                int a = 0, rem = p;
                while (rem >= NT - a) { rem -= NT - a; a++; }
                const int b = a + rem;                 // a <= b

                float d[NQ], X[NQ], Y[NQ], Z[NQ], pre[NQ + 1];
                pre[0] = 1.f;
                #pragma unroll
                for (int q = 0; q < NQ; q++) {
                    const float2 A = cs2[a][q];        // (ca, sa)
                    const float2 B = cs2[b][q];        // (cb, sb)
                    const float p1 = A.x * B.x;        // ca·cb
                    const float p2 = A.y * B.y;        // sa·sb
                    const float p3 = A.y * B.x;        // sa·cb
                    const float p4 = A.x * B.y;        // ca·sb
                    d[q] = p1 + p2;
                    Z[q] = p1 - p2;
                    X[q] = p3 + p4;
                    Y[q] = p3 - p4;
                    pre[q + 1] = pre[q] * d[q];
                }

                float Wr, Wy;
                if (a == b) {
                    Wr = wre[a] * wre[a] + wim[a] * wim[a];           // |w_a|^2
                    Wy = 0.f;
                } else {
                    Wr =  2.f * (wre[a] * wre[b] + wim[a] * wim[b]);  //  2 Re(conj(wa) wb)
                    Wy = -2.f * (wre[a] * wim[b] - wim[a] * wre[b]);  // -2 Im(conj(wa) wb)
                }

                acc[0] += Wr * pre[NQ];                // ||acc||^2 contribution
                float suf = 1.f;
                #pragma unroll
                for (int q = NQ - 1; q >= 0; q--) {
                    const float mm  = pre[q] * suf;    // Prod_{q' != q} d_{q'}
                    suf *= d[q];
                    const float wrm = Wr * mm;
                    const float wym = Wy * mm;
                    acc[1 + 3 * q + 0] += wrm * X[q];
                    acc[1 + 3 * q + 1] += wym * Y[q];
                    acc[1 + 3 * q + 2] += wrm * Z[q];
                }
            }
        }

        // 3-level butterfly: lanes 0..3 end up holding the 4 partials
        #pragma unroll
        for (int m = 0; m < 34; m++) {
            float v = acc[m];
            v += __shfl_xor_sync(0xffffffffu, v, 16);
            v += __shfl_xor_sync(0xffffffffu, v, 8);
            v += __shfl_xor_sync(0xffffffffu, v, 4);
            acc[m] = v;
        }
        if (lane < 4) {
            #pragma unroll
            for (int m = 0; m < 34; m++) part[m][wid * 4 + lane] = acc[m];
        }
    }
    __syncthreads();

    // ---- Phase D: fold 16 partials for numerator and denominator ----
    // den loads are warp-uniform (LDS broadcast, conflict-free).
    if (tid < 33) {
        float num = 0.f, den = 0.f;
        #pragma unroll
        for (int k = 0; k < 16; k++) {
            num += part[tid + 1][k];
            den += part[0][k];
        }
        out[tid] = num / den;
    }
}

}  // namespace

extern "C" void kernel_launch(void* const* d_in, const int* in_sizes, int n_in,
                              void* d_out, int out_size) {
    (void)in_sizes; (void)n_in; (void)out_size;
    quixer_kernel<<<1, 384>>>(
        (const float*)d_in[0],   // tokens_emb [32,512]
        (const float*)d_in[1],   // W_angles   [44,512]
        (const float*)d_in[2],   // b_angles   [44]
        (const float*)d_in[3],   // qsvt_coeffs[3]
        (const float*)d_in[4],   // lcu_re     [32]
        (const float*)d_in[5],   // lcu_im     [32]
        (const float*)d_in[6],   // ff_params  [44]
        (float*)d_out);          // [33]
}

// round 15
// speedup vs baseline: 1.1116x; 1.1116x over previous
#include <cuda_runtime.h>

// QuixerCore — analytic collapse, single fused kernel.
// FINAL (R12 configuration — best measured: 8.256us bench / 6.112us ncu,
// rel_err 8.7e-7. R13's packed-butterfly variant was neutral-to-negative;
// reverted.)
//
// Math (validated R8-R13, rel_err ~9e-7):
//  * CRX blocks are no-ops; only RY params [0..10] and [22..32] act.
//  * Token unitary = product of per-qubit RY with half-angle
//    h[t][q] = (A[t][q] + A[t][q+22]) / 2, A = emb @ W.T + b.
//  * _apply_lcu norm prefactor cancels -> acc = 21 weighted product states
//    (1 e0 + 4 single + 16 double); ff unitary folds in as +h_ff[q].
//  * poly_norm and final normalization cancel in exps = raw / ||acc||^2.
//  * Expectations factorize: per pair (a,b), per qubit:
//      d = ca·cb + sa·sb,  X = sa·cb + ca·sb,  Y = sa·cb − ca·sb,
//      Z = ca·cb − sa·sb;  contribution = W_pair · P · Prod_{q'≠q} d.
//
// Structure (384 threads = 12 warps):
//  warps 0..10 : Phase A — 2 W rows x 4 tokens per warp, 24 LDG.128 batched
//                (264 total LDG, each input line loaded once per warp),
//                FFMA2 accumulation.
//  warp 11     : scalar prep (lcu normalizer, 21 weights, angle bases),
//                fully overlapped with Phase A.
//  barrier -> Phase B: 231 threads, __sincosf, tables stored as float2 (c,s).
//  barrier -> Phase C: 4 warps x 2 pairs/thread. Single pass per pair computes
//                d/X/Y/Z from one float2 LDS pair per qubit (22 LDS/pair),
//                keeps them in registers for the suffix pass. 3-level butterfly
//                (lanes 0..3 hold partials) -> part[34][16].
//  barrier -> Phase D: 33 threads fold 16 partials each and divide.

namespace {

constexpr int NQ    = 11;
constexpr int NT    = 21;    // 1 + 4 + 16 product-state terms
constexpr int NPAIR = 231;   // NT*(NT+1)/2

__device__ __forceinline__ void ffma2(unsigned long long& acc,
                                      unsigned long long a,
                                      unsigned long long b) {
    asm("fma.rn.f32x2 %0, %1, %2, %0;" : "+l"(acc) : "l"(a), "l"(b));
}

__global__ void __launch_bounds__(384, 1) quixer_kernel(
    const float* __restrict__ emb,   // [32,512]
    const float* __restrict__ W,     // [44,512]
    const float* __restrict__ bias,  // [44]
    const float* __restrict__ qc,    // [3]
    const float* __restrict__ lre,   // [32]
    const float* __restrict__ lim,   // [32]
    const float* __restrict__ ffp,   // [44]
    float* __restrict__ out)         // [33]
{
    __shared__ float  rawA[4][22];       // raw dots (no bias); jj<11 -> param jj, else jj+11
    __shared__ float  hb0[NQ];           // ff half-angle base (term 0)
    __shared__ float  hb1[NQ];           // + 1x bias half-sum (terms 1..4)
    __shared__ float  hb2[NQ];           // + 2x bias half-sum (terms 5..20)
    __shared__ float2 cs2[NT][NQ];       // (cos, sin) per term per qubit
    __shared__ float  wre[NT], wim[NT];  // complex term weights
    __shared__ float  part[34][16];      // 4 warps x 4 lane-partials each

    const int tid  = threadIdx.x;
    const int lane = tid & 31;
    const int wid  = tid >> 5;

    if (wid < 11) {
        // ---- Phase A: 2 W rows x 4 tokens per warp; all 24 loads batched ----
        const int jj0 = 2 * wid;
        const int jj1 = 2 * wid + 1;
        const int j0  = (jj0 < NQ) ? jj0 : (jj0 + 11);
        const int j1  = (jj1 < NQ) ? jj1 : (jj1 + 11);
        const ulonglong2* W0 = reinterpret_cast<const ulonglong2*>(W + j0 * 512);
        const ulonglong2* W1 = reinterpret_cast<const ulonglong2*>(W + j1 * 512);

        ulonglong2 wv0[4], wv1[4], ev[4][4];
        #pragma unroll
        for (int k = 0; k < 4; k++) {
            wv0[k] = W0[lane + 32 * k];
            wv1[k] = W1[lane + 32 * k];
        }
        #pragma unroll
        for (int t = 0; t < 4; t++) {
            const ulonglong2* E = reinterpret_cast<const ulonglong2*>(emb + t * 512);
            #pragma unroll
            for (int k = 0; k < 4; k++) ev[t][k] = E[lane + 32 * k];
        }

        unsigned long long a0[4] = {0ull, 0ull, 0ull, 0ull};
        unsigned long long a1[4] = {0ull, 0ull, 0ull, 0ull};
        #pragma unroll
        for (int t = 0; t < 4; t++) {
            #pragma unroll
            for (int k = 0; k < 4; k++) {
                ffma2(a0[t], ev[t][k].x, wv0[k].x);
                ffma2(a0[t], ev[t][k].y, wv0[k].y);
                ffma2(a1[t], ev[t][k].x, wv1[k].x);
                ffma2(a1[t], ev[t][k].y, wv1[k].y);
            }
        }
        #pragma unroll
        for (int t = 0; t < 4; t++) {
            float2 f0 = *reinterpret_cast<float2*>(&a0[t]);
            float2 f1 = *reinterpret_cast<float2*>(&a1[t]);
            float s0 = f0.x + f0.y;
            float s1 = f1.x + f1.y;
            #pragma unroll
            for (int o = 16; o; o >>= 1) {
                s0 += __shfl_xor_sync(0xffffffffu, s0, o);
                s1 += __shfl_xor_sync(0xffffffffu, s1, o);
            }
            if (lane == 0) {
                rawA[t][jj0] = s0;
                rawA[t][jj1] = s1;
            }
        }
    } else {
        // ---- Warp 11: scalar prep, overlapped with Phase A ----
        float lr = lre[lane], li = lim[lane];
        float f1 = 0.f, f2 = 0.f, b1 = 0.f, b2 = 0.f;
        if (lane < NQ) {
            f1 = ffp[lane];  f2 = ffp[lane + 22];
            b1 = bias[lane]; b2 = bias[lane + 22];
        }
        const float q0 = qc[0], q1 = qc[1], q2 = qc[2];

        float v = hypotf(lr, li);
        #pragma unroll
        for (int o = 16; o; o >>= 1) v += __shfl_xor_sync(0xffffffffu, v, o);
        const float invS = 1.f / fmaxf(v, 1e-8f);   // all lanes hold the sum

        if (lane < NQ) {
            float hf = 0.5f * (f1 + f2);            // ff half-angle
            float bh = 0.5f * (b1 + b2);            // bias half-sum
            hb0[lane] = hf;
            hb1[lane] = hf + bh;
            hb2[lane] = hf + 2.f * bh;
        }
        if (lane < NT) {
            const int m = lane;
            float re, im;
            if (m == 0) {
                re = q0; im = 0.f;
            } else if (m < 5) {
                int s4 = m - 1;
                re = q1 * lre[s4] * invS;
                im = q1 * lim[s4] * invS;
            } else {
                int idx = m - 5;
                int t = idx >> 2, s4 = idx & 3;
                float ar = lre[t] * invS, ai = lim[t] * invS;
                float br = lre[s4] * invS, bi = lim[s4] * invS;
                re = q2 * (ar * br - ai * bi);
                im = q2 * (ar * bi + ai * br);
            }
            wre[m] = re;
            wim[m] = im;
        }
    }
    __syncthreads();

    // ---- Phase B: per-term (cos,sin) tables (231 threads), float2 packed ----
    if (tid < NT * NQ) {
        const int term = tid / NQ;
        const int q    = tid - term * NQ;
        float h;
        if (term == 0) {
            h = hb0[q];
        } else if (term < 5) {
            const int t = term - 1;
            h = hb1[q] + 0.5f * (rawA[t][q] + rawA[t][q + 11]);
        } else {
            const int idx = term - 5;
            const int t = idx >> 2, s4 = idx & 3;
            h = hb2[q] + 0.5f * (rawA[t][q] + rawA[t][q + 11])
                       + 0.5f * (rawA[s4][q] + rawA[s4][q + 11]);
        }
        float cv, sv;
        __sincosf(h, &sv, &cv);
        cs2[term][q] = make_float2(cv, sv);
    }
    __syncthreads();

    // ---- Phase C: 4 warps, 2 pairs per thread, single-pass elements ----
    if (wid < 4) {
        float acc[34];
        #pragma unroll
        for (int m = 0; m < 34; m++) acc[m] = 0.f;

        #pragma unroll
        for (int half = 0; half < 2; half++) {
            const int p = tid + 128 * half;
            if (p < NPAIR) {
                int a = 0, rem = p;
                while (rem >= NT - a) { rem -= NT - a; a++; }
                const int b = a + rem;                 // a <= b

                // single pass: one float2 LDS per term per qubit; keep
                // d/X/Y/Z in registers for the suffix pass.
                float d[NQ], X[NQ], Y[NQ], Z[NQ], pre[NQ + 1];
                pre[0] = 1.f;
                #pragma unroll
                for (int q = 0; q < NQ; q++) {
                    const float2 A = cs2[a][q];        // (ca, sa)
                    const float2 B = cs2[b][q];        // (cb, sb)
                    const float p1 = A.x * B.x;        // ca·cb
                    const float p2 = A.y * B.y;        // sa·sb
                    const float p3 = A.y * B.x;        // sa·cb
                    const float p4 = A.x * B.y;        // ca·sb
                    d[q] = p1 + p2;
                    Z[q] = p1 - p2;
                    X[q] = p3 + p4;
                    Y[q] = p3 - p4;
                    pre[q + 1] = pre[q] * d[q];
                }

                float Wr, Wy;
                if (a == b) {
                    Wr = wre[a] * wre[a] + wim[a] * wim[a];           // |w_a|^2
                    Wy = 0.f;
                } else {
                    Wr =  2.f * (wre[a] * wre[b] + wim[a] * wim[b]);  //  2 Re(conj(wa) wb)
                    Wy = -2.f * (wre[a] * wim[b] - wim[a] * wre[b]);  // -2 Im(conj(wa) wb)
                }

                acc[0] += Wr * pre[NQ];                // ||acc||^2 contribution
                float suf = 1.f;
                #pragma unroll
                for (int q = NQ - 1; q >= 0; q--) {
                    const float mm  = pre[q] * suf;    // Prod_{q' != q} d_{q'}
                    suf *= d[q];
                    const float wrm = Wr * mm;
                    const float wym = Wy * mm;
                    acc[1 + 3 * q + 0] += wrm * X[q];
                    acc[1 + 3 * q + 1] += wym * Y[q];
                    acc[1 + 3 * q + 2] += wrm * Z[q];
                }
            }
        }

        // 3-level butterfly: lanes 0..3 end up holding the 4 partials
        #pragma unroll
        for (int m = 0; m < 34; m++) {
            float v = acc[m];
            v += __shfl_xor_sync(0xffffffffu, v, 16);
            v += __shfl_xor_sync(0xffffffffu, v, 8);
            v += __shfl_xor_sync(0xffffffffu, v, 4);
            acc[m] = v;
        }
        if (lane < 4) {
            #pragma unroll
            for (int m = 0; m < 34; m++) part[m][wid * 4 + lane] = acc[m];
        }
    }
    __syncthreads();

    // ---- Phase D: fold 16 partials for numerator and denominator ----
    if (tid < 33) {
        float num = 0.f, den = 0.f;
        #pragma unroll
        for (int k = 0; k < 16; k++) {
            num += part[tid + 1][k];
            den += part[0][k];
        }
        out[tid] = num / den;
    }
}

}  // namespace

extern "C" void kernel_launch(void* const* d_in, const int* in_sizes, int n_in,
                              void* d_out, int out_size) {
    (void)in_sizes; (void)n_in; (void)out_size;
    quixer_kernel<<<1, 384>>>(
        (const float*)d_in[0],   // tokens_emb [32,512]
        (const float*)d_in[1],   // W_angles   [44,512]
        (const float*)d_in[2],   // b_angles   [44]
        (const float*)d_in[3],   // qsvt_coeffs[3]
        (const float*)d_in[4],   // lcu_re     [32]
        (const float*)d_in[5],   // lcu_im     [32]
        (const float*)d_in[6],   // ff_params  [44]
        (float*)d_out);          // [33]
}